// round 2
// baseline (speedup 1.0000x reference)
#include <cuda_runtime.h>
#include <math.h>

// Cl(3,0) Cayley sign table: e_a e_b = SGN[a][b] * e_{a^b}
// sign(a,b) = (-1)^( popc((a>>1)&b) + popc((a>>2)&b) )
__device__ constexpr float SGN[8][8] = {
    { 1, 1, 1, 1, 1, 1, 1, 1},
    { 1, 1, 1, 1, 1, 1, 1, 1},
    { 1,-1, 1,-1, 1,-1, 1,-1},
    { 1,-1, 1,-1, 1,-1, 1,-1},
    { 1,-1,-1, 1, 1,-1,-1, 1},
    { 1,-1,-1, 1, 1,-1,-1, 1},
    { 1, 1,-1,-1, 1, 1,-1,-1},
    { 1, 1,-1,-1, 1, 1,-1,-1}};

// rotor nonzero component indices: scalar, e12, e13, e23
__device__ constexpr int UIDX[4] = {0, 3, 5, 6};

// grade of each multivector component (popcount)
__device__ constexpr int GRADE[8] = {0, 1, 1, 2, 1, 2, 2, 3};

// t = u * v  (u: rotor, components at UIDX; v: full 8)
__device__ __forceinline__ void rotor_left(const float u[4], const float v[8], float t[8]) {
#pragma unroll
    for (int k = 0; k < 8; k++) {
        float s = 0.f;
#pragma unroll
        for (int a = 0; a < 4; a++) {
            const int ai = UIDX[a];
            const int vi = ai ^ k;          // u_ai * v_vi -> component k
            s = fmaf(SGN[ai][vi] * u[a], v[vi], s);
        }
        t[k] = s;
    }
}

// x = t * w  (w: rotor, components at UIDX)
__device__ __forceinline__ void rotor_right(const float t[8], const float w[4], float x[8]) {
#pragma unroll
    for (int m = 0; m < 8; m++) {
        float s = 0.f;
#pragma unroll
        for (int l = 0; l < 4; l++) {
            const int li = UIDX[l];
            const int ti = m ^ li;          // t_ti * w_li -> component m
            s = fmaf(SGN[ti][li] * w[l], t[ti], s);
        }
        x[m] = s;
    }
}

// rotor_exp of bivector (b0,b1,b2) -> components {scalar, e12, e13, e23}
__device__ __forceinline__ void rotor_exp4(float b0, float b1, float b2, float r[4]) {
    float t2 = fmaf(b0, b0, fmaf(b1, b1, b2 * b2));
    float th = sqrtf(t2);
    float sn, cs;
    sincosf(th, &sn, &cs);
    float sinc = (th > 1e-6f) ? sn / fmaxf(th, 1e-6f) : 1.0f;
    r[0] = cs;
    r[1] = sinc * b0;
    r[2] = sinc * b1;
    r[3] = sinc * b2;
}

#define NCH 32
#define BPB 8   // batch rows per block (1 warp each)

__global__ __launch_bounds__(256) void dynamics_kernel(
    const float* __restrict__ state,       // [B, 32, 8]
    const int*   __restrict__ action,      // [B]
    const float* __restrict__ act_bv,      // [5, 3]
    const float* __restrict__ norm_scale,  // [32]
    const float* __restrict__ rotor_bv,    // [32, 3]
    const float* __restrict__ lin_W,       // [32, 32, 4]
    const float* __restrict__ lin_b,       // [32]
    const float* __restrict__ reward_W,    // [1, 32]
    const float* __restrict__ reward_b,    // [1]
    float* __restrict__ out,               // [B] reward, then [B,32,8] next_state
    int B)
{
    // W staged as Wsh[o*129 + i*4 + g]: lane (=o) bank = (o + 4i + g) % 32 -> conflict free
    __shared__ __align__(16) float Wsh[NCH * 129];
    __shared__ __align__(16) float hsh[BPB][NCH][8];
    __shared__ float Rcsh[NCH][4];
    __shared__ float nscs[NCH], lbs[NCH], rWs[NCH];
    __shared__ float abvs[5][3];
    __shared__ float rbs;

    const int tid = threadIdx.x;
    const int c  = tid & 31;   // channel / output channel / lane
    const int bl = tid >> 5;   // local batch row / warp id

    // ---- stage block-invariant params ----
    for (int s = tid; s < NCH * 128; s += 256) {
        Wsh[(s >> 7) * 129 + (s & 127)] = lin_W[s];
    }
    if (tid < NCH) {
        nscs[tid] = norm_scale[tid];
        lbs[tid]  = lin_b[tid];
        rWs[tid]  = reward_W[tid];
        float r[4];
        rotor_exp4(-0.5f * rotor_bv[tid * 3 + 0],
                   -0.5f * rotor_bv[tid * 3 + 1],
                   -0.5f * rotor_bv[tid * 3 + 2], r);
        Rcsh[tid][0] = r[0]; Rcsh[tid][1] = r[1];
        Rcsh[tid][2] = r[2]; Rcsh[tid][3] = r[3];
    }
    if (tid < 15) ((float*)abvs)[tid] = act_bv[tid];
    if (tid == 0) rbs = reward_b[0];
    __syncthreads();

    const int b = blockIdx.x * BPB + bl;
    if (b >= B) return;   // whole warp exits together

    // ---- per-b action rotor ----
    const int act = action[b];
    float u[4];
    rotor_exp4(-0.5f * abvs[act][0], -0.5f * abvs[act][1], -0.5f * abvs[act][2], u);
    const float ur[4] = {u[0], -u[1], -u[2], -u[3]};   // reverse

    // ---- load state[b][c] ----
    float s8[8];
    {
        const float4* sp = (const float4*)(state + (((size_t)b * NCH + c) << 3));
        float4 sA = sp[0], sB = sp[1];
        s8[0] = sA.x; s8[1] = sA.y; s8[2] = sA.z; s8[3] = sA.w;
        s8[4] = sB.x; s8[5] = sB.y; s8[6] = sB.z; s8[7] = sB.w;
    }

    // ---- x = R s R~ ----
    float t8[8], x8[8];
    rotor_left(u, s8, t8);
    rotor_right(t8, ur, x8);

    // ---- RMS-ish norm + scale + erf gate ----
    float nn = 1e-6f;
#pragma unroll
    for (int d = 0; d < 8; d++) nn = fmaf(x8[d], x8[d], nn);
    const float inv = rsqrtf(nn) * nscs[c];
    float h8[8];
#pragma unroll
    for (int d = 0; d < 8; d++) h8[d] = x8[d] * inv;
    const float gate = 0.5f * (1.0f + erff(h8[0] * 0.70710678118654752f));
#pragma unroll
    for (int d = 0; d < 8; d++) h8[d] *= gate;

    // ---- per-channel rotor sandwich ----
    const float uc[4]  = {Rcsh[c][0], Rcsh[c][1], Rcsh[c][2], Rcsh[c][3]};
    const float ucr[4] = {uc[0], -uc[1], -uc[2], -uc[3]};
    rotor_left(uc, h8, t8);
    rotor_right(t8, ucr, h8);

    // ---- share h across the warp (warp-private tile) ----
    *(float4*)&hsh[bl][c][0] = make_float4(h8[0], h8[1], h8[2], h8[3]);
    *(float4*)&hsh[bl][c][4] = make_float4(h8[4], h8[5], h8[6], h8[7]);
    __syncwarp();

    // ---- grade-tied channel mix: acc[d] = x[d] + sum_i h[i][d] * W[o][i][grade(d)] ----
    float acc[8];
#pragma unroll
    for (int d = 0; d < 8; d++) acc[d] = x8[d];
    acc[0] += lbs[c];

#pragma unroll
    for (int i = 0; i < NCH; i++) {
        const float4 hA = *(const float4*)&hsh[bl][i][0];   // broadcast
        const float4 hB = *(const float4*)&hsh[bl][i][4];   // broadcast
        const float* wr = &Wsh[c * 129 + i * 4];
        const float w0 = wr[0], w1 = wr[1], w2 = wr[2], w3 = wr[3];
        acc[0] = fmaf(hA.x, w0, acc[0]);
        acc[1] = fmaf(hA.y, w1, acc[1]);
        acc[2] = fmaf(hA.z, w1, acc[2]);
        acc[3] = fmaf(hA.w, w2, acc[3]);
        acc[4] = fmaf(hB.x, w1, acc[4]);
        acc[5] = fmaf(hB.y, w2, acc[5]);
        acc[6] = fmaf(hB.z, w2, acc[6]);
        acc[7] = fmaf(hB.w, w3, acc[7]);
    }

    // ---- write next_state ----
    float* ns = out + B + (((size_t)b * NCH + c) << 3);
    *(float4*)(ns + 0) = make_float4(acc[0], acc[1], acc[2], acc[3]);
    *(float4*)(ns + 4) = make_float4(acc[4], acc[5], acc[6], acc[7]);

    // ---- reward: warp reduce over channels ----
    float rv = acc[0] * rWs[c];
#pragma unroll
    for (int off = 16; off; off >>= 1) rv += __shfl_xor_sync(0xffffffffu, rv, off);
    if (c == 0) out[b] = rv + rbs;
}

extern "C" void kernel_launch(void* const* d_in, const int* in_sizes, int n_in,
                              void* d_out, int out_size) {
    const float* state      = (const float*)d_in[0];
    const int*   action     = (const int*)  d_in[1];
    const float* act_bv     = (const float*)d_in[2];
    const float* norm_scale = (const float*)d_in[3];
    const float* rotor_bv   = (const float*)d_in[4];
    const float* lin_W      = (const float*)d_in[5];
    const float* lin_b      = (const float*)d_in[6];
    const float* reward_W   = (const float*)d_in[7];
    const float* reward_b   = (const float*)d_in[8];
    float* out = (float*)d_out;

    const int B = in_sizes[1];               // action count
    const int blocks = (B + BPB - 1) / BPB;  // 8 batch rows per block
    dynamics_kernel<<<blocks, 256>>>(state, action, act_bv, norm_scale, rotor_bv,
                                     lin_W, lin_b, reward_W, reward_b, out, B);
}

// round 4
// speedup vs baseline: 1.3191x; 1.3191x over previous
#include <cuda_runtime.h>
#include <math.h>

typedef unsigned long long u64;

// Cl(3,0) Cayley sign table: e_a e_b = SGN[a][b] * e_{a^b}
__device__ constexpr float SGN[8][8] = {
    { 1, 1, 1, 1, 1, 1, 1, 1},
    { 1, 1, 1, 1, 1, 1, 1, 1},
    { 1,-1, 1,-1, 1,-1, 1,-1},
    { 1,-1, 1,-1, 1,-1, 1,-1},
    { 1,-1,-1, 1, 1,-1,-1, 1},
    { 1,-1,-1, 1, 1,-1,-1, 1},
    { 1, 1,-1,-1, 1, 1,-1,-1},
    { 1, 1,-1,-1, 1, 1,-1,-1}};

// rotor nonzero component indices: scalar, e12, e13, e23
__device__ constexpr int UIDX[4] = {0, 3, 5, 6};

__device__ __forceinline__ void rotor_left(const float u[4], const float v[8], float t[8]) {
#pragma unroll
    for (int k = 0; k < 8; k++) {
        float s = 0.f;
#pragma unroll
        for (int a = 0; a < 4; a++) {
            const int ai = UIDX[a];
            const int vi = ai ^ k;
            s = fmaf(SGN[ai][vi] * u[a], v[vi], s);
        }
        t[k] = s;
    }
}

__device__ __forceinline__ void rotor_right(const float t[8], const float w[4], float x[8]) {
#pragma unroll
    for (int m = 0; m < 8; m++) {
        float s = 0.f;
#pragma unroll
        for (int l = 0; l < 4; l++) {
            const int li = UIDX[l];
            const int ti = m ^ li;
            s = fmaf(SGN[ti][li] * w[l], t[ti], s);
        }
        x[m] = s;
    }
}

__device__ __forceinline__ void rotor_exp4(float b0, float b1, float b2, float r[4]) {
    float t2 = fmaf(b0, b0, fmaf(b1, b1, b2 * b2));
    float th = sqrtf(t2);
    float sn, cs;
    sincosf(th, &sn, &cs);
    float sinc = (th > 1e-6f) ? sn / fmaxf(th, 1e-6f) : 1.0f;
    r[0] = cs; r[1] = sinc * b0; r[2] = sinc * b1; r[3] = sinc * b2;
}

// ---- packed f32x2 helpers ----
__device__ __forceinline__ u64 pack2(float lo, float hi) {
    u64 r; asm("mov.b64 %0, {%1, %2};" : "=l"(r) : "f"(lo), "f"(hi)); return r;
}
__device__ __forceinline__ float low2(u64 v) {
    float lo, hi; asm("mov.b64 {%0, %1}, %2;" : "=f"(lo), "=f"(hi) : "l"(v)); return lo;
}
__device__ __forceinline__ void fma2(u64& d, u64 a, u64 b) {
    asm("fma.rn.f32x2 %0, %1, %2, %0;" : "+l"(d) : "l"(a), "l"(b));
}

#define NCH  32
#define WPB  4    // warps per block
#define BPW  4    // batch rows per warp
#define BPB  (WPB * BPW)   // 16 b per block
#define WSTR 132  // W row stride (floats): 16B-aligned, conflict-free LDS.128
#define HSTR 12   // h row stride (floats): 16B-aligned, conflict-free STS.128

__global__ __launch_bounds__(128) void dynamics_kernel(
    const float* __restrict__ state,       // [B, 32, 8]
    const int*   __restrict__ action,      // [B]
    const float* __restrict__ act_bv,      // [5, 3]
    const float* __restrict__ norm_scale,  // [32]
    const float* __restrict__ rotor_bv,    // [32, 3]
    const float* __restrict__ lin_W,       // [32, 32, 4]
    const float* __restrict__ lin_b,       // [32]
    const float* __restrict__ reward_W,    // [1, 32]
    const float* __restrict__ reward_b,    // [1]
    float* __restrict__ out,               // [B] reward, then [B,32,8] next_state
    int B)
{
    __shared__ __align__(16) float Wsh[NCH * WSTR];          // 16.9 KB
    __shared__ __align__(16) float hsh[WPB][BPW][NCH][HSTR]; // 24 KB
    __shared__ float Rcsh[NCH][4];
    __shared__ float nscs[NCH], lbs[NCH], rWs[NCH];
    __shared__ float abvs[5][3];
    __shared__ float rbs;

    const int tid = threadIdx.x;
    const int c   = tid & 31;   // channel (= output channel in matvec)
    const int wid = tid >> 5;

    // ---- stage block-invariant params ----
    for (int s = tid; s < NCH * 128; s += 128) {
        Wsh[(s >> 7) * WSTR + (s & 127)] = lin_W[s];
    }
    if (tid < NCH) {
        nscs[tid] = norm_scale[tid];
        lbs[tid]  = lin_b[tid];
        rWs[tid]  = reward_W[tid];
        float r[4];
        rotor_exp4(-0.5f * rotor_bv[tid * 3 + 0],
                   -0.5f * rotor_bv[tid * 3 + 1],
                   -0.5f * rotor_bv[tid * 3 + 2], r);
        Rcsh[tid][0] = r[0]; Rcsh[tid][1] = r[1];
        Rcsh[tid][2] = r[2]; Rcsh[tid][3] = r[3];
    }
    if (tid < 15) ((float*)abvs)[tid] = act_bv[tid];
    if (tid == 0) rbs = reward_b[0];
    __syncthreads();

    const int b0 = (blockIdx.x * WPB + wid) * BPW;

    // per-channel rotor (same for all j)
    const float uc[4]  = {Rcsh[c][0], Rcsh[c][1], Rcsh[c][2], Rcsh[c][3]};
    const float ucr[4] = {uc[0], -uc[1], -uc[2], -uc[3]};
    const float lbs_c = lbs[c];

    // ---- front-load global reads (MLP) ----
    float4 sA[BPW], sB[BPW];
    int actj[BPW];
#pragma unroll
    for (int j = 0; j < BPW; j++) {
        const int b = min(b0 + j, B - 1);
        actj[j] = action[b];
        const float4* sp = (const float4*)(state + (((size_t)b * NCH + c) << 3));
        sA[j] = sp[0];
        sB[j] = sp[1];
    }

    u64 acc[BPW][4];

    // ---- per-b pipeline: sandwich, norm, gate, channel sandwich ----
#pragma unroll
    for (int j = 0; j < BPW; j++) {
        float u[4];
        rotor_exp4(-0.5f * abvs[actj[j]][0], -0.5f * abvs[actj[j]][1],
                   -0.5f * abvs[actj[j]][2], u);
        const float ur[4] = {u[0], -u[1], -u[2], -u[3]};

        float s8[8] = {sA[j].x, sA[j].y, sA[j].z, sA[j].w,
                       sB[j].x, sB[j].y, sB[j].z, sB[j].w};

        float t8[8], x8[8];
        rotor_left(u, s8, t8);
        rotor_right(t8, ur, x8);

        float nn = 1e-6f;
#pragma unroll
        for (int d = 0; d < 8; d++) nn = fmaf(x8[d], x8[d], nn);
        const float inv = rsqrtf(nn) * nscs[c];
        float h8[8];
#pragma unroll
        for (int d = 0; d < 8; d++) h8[d] = x8[d] * inv;
        const float gate = 0.5f * (1.0f + erff(h8[0] * 0.70710678118654752f));
#pragma unroll
        for (int d = 0; d < 8; d++) h8[d] *= gate;

        rotor_left(uc, h8, t8);
        rotor_right(t8, ucr, h8);

        *(float4*)&hsh[wid][j][c][0] = make_float4(h8[0], h8[1], h8[2], h8[3]);
        *(float4*)&hsh[wid][j][c][4] = make_float4(h8[4], h8[5], h8[6], h8[7]);

        // fold residual (+bias) into accumulators
        acc[j][0] = pack2(x8[0] + lbs_c, x8[1]);
        acc[j][1] = pack2(x8[2], x8[3]);
        acc[j][2] = pack2(x8[4], x8[5]);
        acc[j][3] = pack2(x8[6], x8[7]);
    }
    __syncwarp();

    // ---- grade-tied channel mix, W amortized over 4 b, packed FFMA2 ----
    // weight per d: [w0, w1, w1, w2, w1, w2, w2, w3]
#pragma unroll
    for (int i = 0; i < NCH; i++) {
        const float4 w = *(const float4*)&Wsh[c * WSTR + i * 4];
        const u64 w01 = pack2(w.x, w.y);
        const u64 w12 = pack2(w.y, w.z);
        const u64 w23 = pack2(w.z, w.w);
#pragma unroll
        for (int j = 0; j < BPW; j++) {
            const ulonglong2 hA = *(const ulonglong2*)&hsh[wid][j][i][0]; // broadcast
            const ulonglong2 hB = *(const ulonglong2*)&hsh[wid][j][i][4]; // broadcast
            fma2(acc[j][0], hA.x, w01);
            fma2(acc[j][1], hA.y, w12);
            fma2(acc[j][2], hB.x, w12);
            fma2(acc[j][3], hB.y, w23);
        }
    }

    // ---- write next_state + reward ----
    const float rw = rWs[c];
#pragma unroll
    for (int j = 0; j < BPW; j++) {
        const int b = b0 + j;
        if (b < B) {
            float* ns = out + B + (((size_t)b * NCH + c) << 3);
            ulonglong2 v0; v0.x = acc[j][0]; v0.y = acc[j][1];
            ulonglong2 v1; v1.x = acc[j][2]; v1.y = acc[j][3];
            *(ulonglong2*)(ns + 0) = v0;
            *(ulonglong2*)(ns + 4) = v1;

            float rv = low2(acc[j][0]) * rw;
#pragma unroll
            for (int off = 16; off; off >>= 1) rv += __shfl_xor_sync(0xffffffffu, rv, off);
            if (c == 0) out[b] = rv + rbs;
        }
    }
}

extern "C" void kernel_launch(void* const* d_in, const int* in_sizes, int n_in,
                              void* d_out, int out_size) {
    const float* state      = (const float*)d_in[0];
    const int*   action     = (const int*)  d_in[1];
    const float* act_bv     = (const float*)d_in[2];
    const float* norm_scale = (const float*)d_in[3];
    const float* rotor_bv   = (const float*)d_in[4];
    const float* lin_W      = (const float*)d_in[5];
    const float* lin_b      = (const float*)d_in[6];
    const float* reward_W   = (const float*)d_in[7];
    const float* reward_b   = (const float*)d_in[8];
    float* out = (float*)d_out;

    const int B = in_sizes[1];               // action count
    const int blocks = (B + BPB - 1) / BPB;  // 16 batch rows per block
    dynamics_kernel<<<blocks, 128>>>(state, action, act_bv, norm_scale, rotor_bv,
                                     lin_W, lin_b, reward_W, reward_b, out, B);
}

// round 5
// speedup vs baseline: 1.3229x; 1.0029x over previous
#include <cuda_runtime.h>
#include <math.h>

typedef unsigned long long u64;

// Cl(3,0) Cayley sign table: e_a e_b = SGN[a][b] * e_{a^b}
__device__ constexpr float SGN[8][8] = {
    { 1, 1, 1, 1, 1, 1, 1, 1},
    { 1, 1, 1, 1, 1, 1, 1, 1},
    { 1,-1, 1,-1, 1,-1, 1,-1},
    { 1,-1, 1,-1, 1,-1, 1,-1},
    { 1,-1,-1, 1, 1,-1,-1, 1},
    { 1,-1,-1, 1, 1,-1,-1, 1},
    { 1, 1,-1,-1, 1, 1,-1,-1},
    { 1, 1,-1,-1, 1, 1,-1,-1}};

__device__ constexpr int UIDX[4] = {0, 3, 5, 6};

__device__ __forceinline__ void rotor_left(const float u[4], const float v[8], float t[8]) {
#pragma unroll
    for (int k = 0; k < 8; k++) {
        float s = 0.f;
#pragma unroll
        for (int a = 0; a < 4; a++) {
            const int ai = UIDX[a];
            const int vi = ai ^ k;
            s = fmaf(SGN[ai][vi] * u[a], v[vi], s);
        }
        t[k] = s;
    }
}

__device__ __forceinline__ void rotor_right(const float t[8], const float w[4], float x[8]) {
#pragma unroll
    for (int m = 0; m < 8; m++) {
        float s = 0.f;
#pragma unroll
        for (int l = 0; l < 4; l++) {
            const int li = UIDX[l];
            const int ti = m ^ li;
            s = fmaf(SGN[ti][li] * w[l], t[ti], s);
        }
        x[m] = s;
    }
}

__device__ __forceinline__ void rotor_exp4(float b0, float b1, float b2, float r[4]) {
    float t2 = fmaf(b0, b0, fmaf(b1, b1, b2 * b2));
    float th = sqrtf(t2);
    float sn, cs;
    sincosf(th, &sn, &cs);
    float sinc = (th > 1e-6f) ? sn / fmaxf(th, 1e-6f) : 1.0f;
    r[0] = cs; r[1] = sinc * b0; r[2] = sinc * b1; r[3] = sinc * b2;
}

__device__ __forceinline__ u64 pack2(float lo, float hi) {
    u64 r; asm("mov.b64 %0, {%1, %2};" : "=l"(r) : "f"(lo), "f"(hi)); return r;
}
__device__ __forceinline__ float low2(u64 v) {
    float lo, hi; asm("mov.b64 {%0, %1}, %2;" : "=f"(lo), "=f"(hi) : "l"(v)); return lo;
}
__device__ __forceinline__ void fma2(u64& d, u64 a, u64 b) {
    asm("fma.rn.f32x2 %0, %1, %2, %0;" : "+l"(d) : "l"(a), "l"(b));
}

#define NCH  32
#define WPB  4            // warps per block
#define BPW  4            // batch rows per warp (j)
#define BPB  (WPB * BPW)  // 16 b per block
#define JSTR 392          // h j-stride in floats: 32*12 + 8  (== 8 mod 32 banks, 16B aligned)
#define CSTR 12           // h channel stride in floats (16B aligned, bank-spread)

__global__ __launch_bounds__(128) void dynamics_kernel(
    const float* __restrict__ state,       // [B, 32, 8]
    const int*   __restrict__ action,      // [B]
    const float* __restrict__ act_bv,      // [5, 3]
    const float* __restrict__ norm_scale,  // [32]
    const float* __restrict__ rotor_bv,    // [32, 3]
    const float* __restrict__ lin_W,       // [32, 32, 4]
    const float* __restrict__ lin_b,       // [32]
    const float* __restrict__ reward_W,    // [1, 32]
    const float* __restrict__ reward_b,    // [1]
    float* __restrict__ out,               // [B] reward, then [B,32,8] next_state
    int B)
{
    // W transposed: WT[i][o][k] — per (i, o-octet) a contiguous 128B row => 1 wavefront
    __shared__ __align__(16) float WT[NCH * NCH * 4];        // 16 KB
    __shared__ __align__(16) float hs[WPB][BPW * JSTR];      // 24.5 KB
    __shared__ float Rcsh[NCH][4];
    __shared__ float nscs[NCH], lbs[NCH], rWs[NCH];
    __shared__ float abvs[5][3];
    __shared__ float rbs;

    const int tid  = threadIdx.x;
    const int lane = tid & 31;
    const int wid  = tid >> 5;
    const int j    = lane >> 3;   // batch row within warp
    const int og   = lane & 7;    // output/channel octet index

    // ---- stage params ----
    for (int s = tid; s < NCH * 128; s += 128) {
        const int o = s >> 7, i = (s >> 2) & 31, k = s & 3;
        WT[i * 128 + o * 4 + k] = lin_W[s];
    }
    if (tid < NCH) {
        nscs[tid] = norm_scale[tid];
        lbs[tid]  = lin_b[tid];
        rWs[tid]  = reward_W[tid];
        float r[4];
        rotor_exp4(-0.5f * rotor_bv[tid * 3 + 0],
                   -0.5f * rotor_bv[tid * 3 + 1],
                   -0.5f * rotor_bv[tid * 3 + 2], r);
        Rcsh[tid][0] = r[0]; Rcsh[tid][1] = r[1];
        Rcsh[tid][2] = r[2]; Rcsh[tid][3] = r[3];
    }
    if (tid < 15) ((float*)abvs)[tid] = act_bv[tid];
    if (tid == 0) rbs = reward_b[0];
    __syncthreads();

    float* hw = &hs[wid][0];

    int b = blockIdx.x * BPB + wid * BPW + j;
    const bool valid = (b < B);
    b = valid ? b : (B - 1);

    // ---- action rotor for this lane's batch row ----
    const int act = action[b];
    float u[4];
    rotor_exp4(-0.5f * abvs[act][0], -0.5f * abvs[act][1], -0.5f * abvs[act][2], u);
    const float ur[4] = {u[0], -u[1], -u[2], -u[3]};

    // ---- front-load state for this lane's 4 channels c = og + 8r ----
    float4 sA[4], sB[4];
#pragma unroll
    for (int r = 0; r < 4; r++) {
        const int c = og + 8 * r;
        const float4* sp = (const float4*)(state + (((size_t)b * NCH + c) << 3));
        sA[r] = sp[0];
        sB[r] = sp[1];
    }

    u64 acc[4][4];

    // ---- pre-work: sandwich, norm, gate, channel sandwich; x stays in-lane ----
#pragma unroll
    for (int r = 0; r < 4; r++) {
        const int c = og + 8 * r;
        float s8[8] = {sA[r].x, sA[r].y, sA[r].z, sA[r].w,
                       sB[r].x, sB[r].y, sB[r].z, sB[r].w};

        float t8[8], x8[8];
        rotor_left(u, s8, t8);
        rotor_right(t8, ur, x8);

        float nn = 1e-6f;
#pragma unroll
        for (int d = 0; d < 8; d++) nn = fmaf(x8[d], x8[d], nn);
        const float inv = rsqrtf(nn) * nscs[c];
        float h8[8];
#pragma unroll
        for (int d = 0; d < 8; d++) h8[d] = x8[d] * inv;
        const float gate = 0.5f * (1.0f + erff(h8[0] * 0.70710678118654752f));
#pragma unroll
        for (int d = 0; d < 8; d++) h8[d] *= gate;

        const float uc[4]  = {Rcsh[c][0], Rcsh[c][1], Rcsh[c][2], Rcsh[c][3]};
        const float ucr[4] = {uc[0], -uc[1], -uc[2], -uc[3]};
        rotor_left(uc, h8, t8);
        rotor_right(t8, ucr, h8);

        float* hp = hw + j * JSTR + c * CSTR;
        *(float4*)(hp + 0) = make_float4(h8[0], h8[1], h8[2], h8[3]);
        *(float4*)(hp + 4) = make_float4(h8[4], h8[5], h8[6], h8[7]);

        // residual + bias folded into accumulators
        acc[r][0] = pack2(x8[0] + lbs[c], x8[1]);
        acc[r][1] = pack2(x8[2], x8[3]);
        acc[r][2] = pack2(x8[4], x8[5]);
        acc[r][3] = pack2(x8[6], x8[7]);
    }
    __syncwarp();

    // ---- grade-tied channel mix ----
    // h read: 2 LDS.128, 4 distinct j addresses (1 wf each)
    // W read: 4 LDS.128, each a contiguous 128B octet row (1 wf each)
#pragma unroll
    for (int i = 0; i < NCH; i++) {
        const float* hp = hw + j * JSTR + i * CSTR;
        const ulonglong2 hA = *(const ulonglong2*)(hp + 0);  // (d0,d1),(d2,d3)
        const ulonglong2 hB = *(const ulonglong2*)(hp + 4);  // (d4,d5),(d6,d7)
#pragma unroll
        for (int r = 0; r < 4; r++) {
            const float4 w = *(const float4*)&WT[i * 128 + (og + 8 * r) * 4];
            const u64 w01 = pack2(w.x, w.y);
            const u64 w12 = pack2(w.y, w.z);
            const u64 w23 = pack2(w.z, w.w);
            fma2(acc[r][0], hA.x, w01);
            fma2(acc[r][1], hA.y, w12);
            fma2(acc[r][2], hB.x, w12);
            fma2(acc[r][3], hB.y, w23);
        }
    }

    // ---- write next_state ----
    if (valid) {
#pragma unroll
        for (int r = 0; r < 4; r++) {
            const int c = og + 8 * r;
            float* ns = out + B + (((size_t)b * NCH + c) << 3);
            ulonglong2 v0; v0.x = acc[r][0]; v0.y = acc[r][1];
            ulonglong2 v1; v1.x = acc[r][2]; v1.y = acc[r][3];
            *(ulonglong2*)(ns + 0) = v0;
            *(ulonglong2*)(ns + 4) = v1;
        }
    }

    // ---- reward: partial over this lane's 4 outputs, reduce over og (lane bits 0..2) ----
    float rv = 0.f;
#pragma unroll
    for (int r = 0; r < 4; r++) rv = fmaf(low2(acc[r][0]), rWs[og + 8 * r], rv);
#pragma unroll
    for (int off = 4; off; off >>= 1) rv += __shfl_xor_sync(0xffffffffu, rv, off);
    if (og == 0 && valid) out[b] = rv + rbs;
}

extern "C" void kernel_launch(void* const* d_in, const int* in_sizes, int n_in,
                              void* d_out, int out_size) {
    const float* state      = (const float*)d_in[0];
    const int*   action     = (const int*)  d_in[1];
    const float* act_bv     = (const float*)d_in[2];
    const float* norm_scale = (const float*)d_in[3];
    const float* rotor_bv   = (const float*)d_in[4];
    const float* lin_W      = (const float*)d_in[5];
    const float* lin_b      = (const float*)d_in[6];
    const float* reward_W   = (const float*)d_in[7];
    const float* reward_b   = (const float*)d_in[8];
    float* out = (float*)d_out;

    const int B = in_sizes[1];               // action count
    const int blocks = (B + BPB - 1) / BPB;  // 16 batch rows per block
    dynamics_kernel<<<blocks, 128>>>(state, action, act_bv, norm_scale, rotor_bv,
                                     lin_W, lin_b, reward_W, reward_b, out, B);
}

// round 6
// speedup vs baseline: 1.3903x; 1.0509x over previous
#include <cuda_runtime.h>
#include <math.h>

typedef unsigned long long u64;

// ---- packed f32x2 helpers ----
__device__ __forceinline__ u64 pack2(float lo, float hi) {
    u64 r; asm("mov.b64 %0, {%1, %2};" : "=l"(r) : "f"(lo), "f"(hi)); return r;
}
__device__ __forceinline__ float low2(u64 v) {
    float lo, hi; asm("mov.b64 {%0, %1}, %2;" : "=f"(lo), "=f"(hi) : "l"(v)); return lo;
}
__device__ __forceinline__ void fma2(u64& d, u64 a, u64 b) {
    asm("fma.rn.f32x2 %0, %1, %2, %0;" : "+l"(d) : "l"(a), "l"(b));
}

// rotor_exp of bivector -> components {scalar, e12, e13, e23}
__device__ __forceinline__ void rotor_exp4(float b0, float b1, float b2, float r[4]) {
    float t2 = fmaf(b0, b0, fmaf(b1, b1, b2 * b2));
    float th = sqrtf(t2);
    float sn, cs;
    sincosf(th, &sn, &cs);
    float sinc = (th > 1e-6f) ? sn / fmaxf(th, 1e-6f) : 1.0f;
    r[0] = cs; r[1] = sinc * b0; r[2] = sinc * b1; r[3] = sinc * b2;
}

// 3x3 rotation matrix from unit rotor u = (scalar, e12, e13, e23).
// q = (w,x,y,z) = (u0, -u3, u2, -u1); standard quaternion matrix.
// Acts on vector comps (idx1,idx2,idx4) and on bivector dual d=(s6,-s5,s3).
__device__ __forceinline__ void rotor_to_mat(const float u[4], float m[9]) {
    const float qw = u[0], qx = -u[3], qy = u[2], qz = -u[1];
    const float x2 = qx + qx, y2 = qy + qy, z2 = qz + qz;
    const float xx = qx * x2, yy = qy * y2, zz = qz * z2;
    const float xy = qx * y2, xz = qx * z2, yz = qy * z2;
    const float wx = qw * x2, wy = qw * y2, wz = qw * z2;
    m[0] = 1.f - (yy + zz); m[1] = xy - wz;        m[2] = xz + wy;
    m[3] = xy + wz;         m[4] = 1.f - (xx + zz); m[5] = yz - wx;
    m[6] = xz - wy;         m[7] = yz + wx;        m[8] = 1.f - (xx + yy);
}

__device__ __forceinline__ void mat_apply(const float4 A0, const float4 A1, const float A2,
                                          float v1, float v2, float v3,
                                          float& o1, float& o2, float& o3) {
    o1 = fmaf(A0.x, v1, fmaf(A0.y, v2, A0.z * v3));
    o2 = fmaf(A0.w, v1, fmaf(A1.x, v2, A1.y * v3));
    o3 = fmaf(A1.z, v1, fmaf(A1.w, v2, A2  * v3));
}

#define NCH  32
#define WPB  8            // warps per block
#define BPW  4            // batch rows per warp (j)
#define BPB  (WPB * BPW)  // 32 b per block
#define JSTR 392          // h j-stride (floats): ==8 mod 32 banks, 16B aligned
#define CSTR 12           // h channel stride (floats)

// dynamic smem layout (float offsets)
#define OFF_WT   0                       // 4096
#define OFF_HS   4096                    // WPB*BPW*JSTR = 12544
#define OFF_MC   (OFF_HS + WPB*BPW*JSTR) // 16640: 32*12
#define OFF_MA   (OFF_MC + 384)          // 17024: 8*12 (5 used)
#define OFF_NSC  (OFF_MA + 96)           // 17120
#define OFF_LB   (OFF_NSC + 32)
#define OFF_RW   (OFF_LB + 32)
#define OFF_RB   (OFF_RW + 32)
#define SMEM_FLOATS (OFF_RB + 4)
#define SMEM_BYTES  (SMEM_FLOATS * 4)

__global__ __launch_bounds__(256, 3) void dynamics_kernel(
    const float* __restrict__ state,       // [B, 32, 8]
    const int*   __restrict__ action,      // [B]
    const float* __restrict__ act_bv,      // [5, 3]
    const float* __restrict__ norm_scale,  // [32]
    const float* __restrict__ rotor_bv,    // [32, 3]
    const float* __restrict__ lin_W,       // [32, 32, 4]
    const float* __restrict__ lin_b,       // [32]
    const float* __restrict__ reward_W,    // [1, 32]
    const float* __restrict__ reward_b,    // [1]
    float* __restrict__ out,               // [B] reward, then [B,32,8] next_state
    int B)
{
    extern __shared__ __align__(16) float dsm[];
    float* WT  = dsm + OFF_WT;   // WT[i*128 + o*4 + k]
    float* HS  = dsm + OFF_HS;
    float* MC  = dsm + OFF_MC;   // MC[c*12 + 0..8]
    float* MA  = dsm + OFF_MA;   // MA[a*12 + 0..8]
    float* NSC = dsm + OFF_NSC;
    float* LB  = dsm + OFF_LB;
    float* RW  = dsm + OFF_RW;
    float* RB  = dsm + OFF_RB;

    const int tid  = threadIdx.x;
    const int lane = tid & 31;
    const int wid  = tid >> 5;
    const int j    = lane >> 3;   // batch row within warp
    const int og   = lane & 7;    // channel octet index

    // ---- stage params ----
    for (int s = tid; s < NCH * 128; s += 256) {
        const int o = s >> 7, i = (s >> 2) & 31, k = s & 3;
        WT[i * 128 + o * 4 + k] = lin_W[s];
    }
    if (tid < NCH) {
        NSC[tid] = norm_scale[tid];
        LB[tid]  = lin_b[tid];
        RW[tid]  = reward_W[tid];
        float r[4], m[9];
        rotor_exp4(-0.5f * rotor_bv[tid * 3 + 0],
                   -0.5f * rotor_bv[tid * 3 + 1],
                   -0.5f * rotor_bv[tid * 3 + 2], r);
        rotor_to_mat(r, m);
#pragma unroll
        for (int e = 0; e < 9; e++) MC[tid * 12 + e] = m[e];
    }
    if (tid >= 32 && tid < 37) {
        const int a = tid - 32;
        float r[4], m[9];
        rotor_exp4(-0.5f * act_bv[a * 3 + 0],
                   -0.5f * act_bv[a * 3 + 1],
                   -0.5f * act_bv[a * 3 + 2], r);
        rotor_to_mat(r, m);
#pragma unroll
        for (int e = 0; e < 9; e++) MA[a * 12 + e] = m[e];
    }
    if (tid == 40) RB[0] = reward_b[0];
    __syncthreads();

    float* hw = HS + wid * (BPW * JSTR);

    int b = blockIdx.x * BPB + wid * BPW + j;
    const bool valid = (b < B);
    b = valid ? b : (B - 1);

    // ---- action rotation matrix for this lane's batch row ----
    const int act = action[b];
    const float4 A0 = *(const float4*)&MA[act * 12 + 0];  // m0 m1 m2 m3
    const float4 A1 = *(const float4*)&MA[act * 12 + 4];  // m4 m5 m6 m7
    const float  A2 = MA[act * 12 + 8];                   // m8

    // ---- front-load state for this lane's 4 channels c = og + 8r ----
    float4 sA[4], sB[4];
#pragma unroll
    for (int r = 0; r < 4; r++) {
        const int c = og + 8 * r;
        const float4* sp = (const float4*)(state + (((size_t)b * NCH + c) << 3));
        sA[r] = sp[0];
        sB[r] = sp[1];
    }

    u64 acc[4][4];

    // ---- prework: action sandwich (matrix), norm, gate, channel sandwich (matrix) ----
#pragma unroll
    for (int r = 0; r < 4; r++) {
        const int c = og + 8 * r;
        // s8: idx 0..7
        const float s0 = sA[r].x, s1 = sA[r].y, s2 = sA[r].z, s3 = sA[r].w;
        const float s4 = sB[r].x, s5 = sB[r].y, s6 = sB[r].z, s7 = sB[r].w;

        // x = R s R~ : scalar/pseudo pass through; vector & dual-bivector rotate by A
        float xv1, xv2, xv3, xb1, xb2, xb3;
        mat_apply(A0, A1, A2, s1, s2, s4, xv1, xv2, xv3);
        mat_apply(A0, A1, A2, s6, -s5, s3, xb1, xb2, xb3);
        const float x0 = s0, x1 = xv1, x2 = xv2, x3 = xb3,
                    x4 = xv3, x5 = -xb2, x6 = xb1, x7 = s7;

        // norm + scale + erf gate
        float nn = 1e-6f;
        nn = fmaf(x0, x0, nn); nn = fmaf(x1, x1, nn);
        nn = fmaf(x2, x2, nn); nn = fmaf(x3, x3, nn);
        nn = fmaf(x4, x4, nn); nn = fmaf(x5, x5, nn);
        nn = fmaf(x6, x6, nn); nn = fmaf(x7, x7, nn);
        const float inv = rsqrtf(nn) * NSC[c];
        const float g0 = x0 * inv;
        const float gate = 0.5f * (1.0f + erff(g0 * 0.70710678118654752f));
        const float sc = inv * gate;
        const float h0 = x0 * sc, h1 = x1 * sc, h2 = x2 * sc, h3 = x3 * sc;
        const float h4 = x4 * sc, h5 = x5 * sc, h6 = x6 * sc, h7 = x7 * sc;

        // channel sandwich via precomputed matrix
        const float4 C0 = *(const float4*)&MC[c * 12 + 0];
        const float4 C1 = *(const float4*)&MC[c * 12 + 4];
        const float  C2 = MC[c * 12 + 8];
        float yv1, yv2, yv3, yb1, yb2, yb3;
        mat_apply(C0, C1, C2, h1, h2, h4, yv1, yv2, yv3);
        mat_apply(C0, C1, C2, h6, -h5, h3, yb1, yb2, yb3);

        float* hp = hw + j * JSTR + c * CSTR;
        *(float4*)(hp + 0) = make_float4(h0, yv1, yv2, yb3);
        *(float4*)(hp + 4) = make_float4(yv3, -yb2, yb1, h7);

        // residual + bias folded into accumulators
        acc[r][0] = pack2(x0 + LB[c], x1);
        acc[r][1] = pack2(x2, x3);
        acc[r][2] = pack2(x4, x5);
        acc[r][3] = pack2(x6, x7);
    }
    __syncwarp();

    // ---- grade-tied channel mix (weights per d-pair: w01, w12, w12, w23) ----
#pragma unroll
    for (int i = 0; i < NCH; i++) {
        const float* hp = hw + j * JSTR + i * CSTR;
        const ulonglong2 hA = *(const ulonglong2*)(hp + 0);  // (d0,d1),(d2,d3)
        const ulonglong2 hB = *(const ulonglong2*)(hp + 4);  // (d4,d5),(d6,d7)
#pragma unroll
        for (int r = 0; r < 4; r++) {
            const float4 w = *(const float4*)&WT[i * 128 + (og + 8 * r) * 4];
            const u64 w01 = pack2(w.x, w.y);
            const u64 w12 = pack2(w.y, w.z);
            const u64 w23 = pack2(w.z, w.w);
            fma2(acc[r][0], hA.x, w01);
            fma2(acc[r][1], hA.y, w12);
            fma2(acc[r][2], hB.x, w12);
            fma2(acc[r][3], hB.y, w23);
        }
    }

    // ---- write next_state ----
    if (valid) {
#pragma unroll
        for (int r = 0; r < 4; r++) {
            const int c = og + 8 * r;
            float* ns = out + B + (((size_t)b * NCH + c) << 3);
            ulonglong2 v0; v0.x = acc[r][0]; v0.y = acc[r][1];
            ulonglong2 v1; v1.x = acc[r][2]; v1.y = acc[r][3];
            *(ulonglong2*)(ns + 0) = v0;
            *(ulonglong2*)(ns + 4) = v1;
        }
    }

    // ---- reward: partial over this lane's 4 outputs, reduce over og lanes ----
    float rv = 0.f;
#pragma unroll
    for (int r = 0; r < 4; r++) rv = fmaf(low2(acc[r][0]), RW[og + 8 * r], rv);
#pragma unroll
    for (int off = 4; off; off >>= 1) rv += __shfl_xor_sync(0xffffffffu, rv, off);
    if (og == 0 && valid) out[b] = rv + RB[0];
}

extern "C" void kernel_launch(void* const* d_in, const int* in_sizes, int n_in,
                              void* d_out, int out_size) {
    const float* state      = (const float*)d_in[0];
    const int*   action     = (const int*)  d_in[1];
    const float* act_bv     = (const float*)d_in[2];
    const float* norm_scale = (const float*)d_in[3];
    const float* rotor_bv   = (const float*)d_in[4];
    const float* lin_W      = (const float*)d_in[5];
    const float* lin_b      = (const float*)d_in[6];
    const float* reward_W   = (const float*)d_in[7];
    const float* reward_b   = (const float*)d_in[8];
    float* out = (float*)d_out;

    const int B = in_sizes[1];               // action count
    const int blocks = (B + BPB - 1) / BPB;  // 32 batch rows per block

    cudaFuncSetAttribute(dynamics_kernel,
                         cudaFuncAttributeMaxDynamicSharedMemorySize, SMEM_BYTES);
    dynamics_kernel<<<blocks, 256, SMEM_BYTES>>>(state, action, act_bv, norm_scale,
                                                 rotor_bv, lin_W, lin_b, reward_W,
                                                 reward_b, out, B);
}

// round 8
// speedup vs baseline: 1.6120x; 1.1595x over previous
#include <cuda_runtime.h>
#include <math.h>

typedef unsigned long long u64;

// ---- packed f32x2 helpers ----
__device__ __forceinline__ u64 pack2(float lo, float hi) {
    u64 r; asm("mov.b64 %0, {%1, %2};" : "=l"(r) : "f"(lo), "f"(hi)); return r;
}
__device__ __forceinline__ float low2(u64 v) {
    float lo, hi; asm("mov.b64 {%0, %1}, %2;" : "=f"(lo), "=f"(hi) : "l"(v)); return lo;
}
__device__ __forceinline__ void fma2(u64& d, u64 a, u64 b) {
    asm("fma.rn.f32x2 %0, %1, %2, %0;" : "+l"(d) : "l"(a), "l"(b));
}

// rotor_exp of bivector -> components {scalar, e12, e13, e23}
__device__ __forceinline__ void rotor_exp4(float b0, float b1, float b2, float r[4]) {
    float t2 = fmaf(b0, b0, fmaf(b1, b1, b2 * b2));
    float th = sqrtf(t2);
    float sn, cs;
    sincosf(th, &sn, &cs);
    float sinc = (th > 1e-6f) ? sn / fmaxf(th, 1e-6f) : 1.0f;
    r[0] = cs; r[1] = sinc * b0; r[2] = sinc * b1; r[3] = sinc * b2;
}

// 3x3 rotation matrix from unit rotor u = (scalar, e12, e13, e23).
__device__ __forceinline__ void rotor_to_mat(const float u[4], float m[9]) {
    const float qw = u[0], qx = -u[3], qy = u[2], qz = -u[1];
    const float x2 = qx + qx, y2 = qy + qy, z2 = qz + qz;
    const float xx = qx * x2, yy = qy * y2, zz = qz * z2;
    const float xy = qx * y2, xz = qx * z2, yz = qy * z2;
    const float wx = qw * x2, wy = qw * y2, wz = qw * z2;
    m[0] = 1.f - (yy + zz); m[1] = xy - wz;        m[2] = xz + wy;
    m[3] = xy + wz;         m[4] = 1.f - (xx + zz); m[5] = yz - wx;
    m[6] = xz - wy;         m[7] = yz + wx;        m[8] = 1.f - (xx + yy);
}

__device__ __forceinline__ void mat_apply(const float4 A0, const float4 A1, const float A2,
                                          float v1, float v2, float v3,
                                          float& o1, float& o2, float& o3) {
    o1 = fmaf(A0.x, v1, fmaf(A0.y, v2, A0.z * v3));
    o2 = fmaf(A0.w, v1, fmaf(A1.x, v2, A1.y * v3));
    o3 = fmaf(A1.z, v1, fmaf(A1.w, v2, A2  * v3));
}

#define NCH  32
#define WPB  4            // warps per block (128 threads)
#define BPW  8            // batch rows per warp (2 per lane)
#define BPB  (WPB * BPW)  // 32 b per block
#define JSTR 392          // h row stride (floats): ==8 mod 32 banks, 16B aligned
#define CSTR 12           // h channel stride (floats)

// dynamic smem layout (float offsets)
#define OFF_WT   0                       // 4096
#define OFF_HS   4096                    // WPB*BPW*JSTR = 12544
#define OFF_MC   (OFF_HS + WPB*BPW*JSTR) // 32*12
#define OFF_MA   (OFF_MC + 384)          // 8*12 (5 used)
#define OFF_NSC  (OFF_MA + 96)
#define OFF_LB   (OFF_NSC + 32)
#define OFF_RW   (OFF_LB + 32)
#define OFF_RB   (OFF_RW + 32)
#define SMEM_FLOATS (OFF_RB + 4)
#define SMEM_BYTES  (SMEM_FLOATS * 4)

__global__ __launch_bounds__(128, 3) void dynamics_kernel(
    const float* __restrict__ state,       // [B, 32, 8]
    const int*   __restrict__ action,      // [B]
    const float* __restrict__ act_bv,      // [5, 3]
    const float* __restrict__ norm_scale,  // [32]
    const float* __restrict__ rotor_bv,    // [32, 3]
    const float* __restrict__ lin_W,       // [32, 32, 4]
    const float* __restrict__ lin_b,       // [32]
    const float* __restrict__ reward_W,    // [1, 32]
    const float* __restrict__ reward_b,    // [1]
    float* __restrict__ out,               // [B] reward, then [B,32,8] next_state
    int B)
{
    extern __shared__ __align__(16) float dsm[];
    float* WT  = dsm + OFF_WT;   // WT[i*128 + o*4 + k]
    float* HS  = dsm + OFF_HS;
    float* MC  = dsm + OFF_MC;   // MC[c*12 + 0..8]
    float* MA  = dsm + OFF_MA;   // MA[a*12 + 0..8]
    float* NSC = dsm + OFF_NSC;
    float* LB  = dsm + OFF_LB;
    float* RW  = dsm + OFF_RW;
    float* RB  = dsm + OFF_RB;

    const int tid  = threadIdx.x;
    const int lane = tid & 31;
    const int wid  = tid >> 5;
    const int j    = lane >> 3;   // batch row within warp (pass adds +4)
    const int og   = lane & 7;    // channel octet index

    // ---- stage params ----
    for (int s = tid; s < NCH * 128; s += 128) {
        const int o = s >> 7, i = (s >> 2) & 31, k = s & 3;
        WT[i * 128 + o * 4 + k] = lin_W[s];
    }
    if (tid < NCH) {
        NSC[tid] = norm_scale[tid];
        LB[tid]  = lin_b[tid];
        RW[tid]  = reward_W[tid];
        float r[4], m[9];
        rotor_exp4(-0.5f * rotor_bv[tid * 3 + 0],
                   -0.5f * rotor_bv[tid * 3 + 1],
                   -0.5f * rotor_bv[tid * 3 + 2], r);
        rotor_to_mat(r, m);
#pragma unroll
        for (int e = 0; e < 9; e++) MC[tid * 12 + e] = m[e];
    }
    if (tid >= 32 && tid < 37) {
        const int a = tid - 32;
        float r[4], m[9];
        rotor_exp4(-0.5f * act_bv[a * 3 + 0],
                   -0.5f * act_bv[a * 3 + 1],
                   -0.5f * act_bv[a * 3 + 2], r);
        rotor_to_mat(r, m);
#pragma unroll
        for (int e = 0; e < 9; e++) MA[a * 12 + e] = m[e];
    }
    if (tid == 40) RB[0] = reward_b[0];
    __syncthreads();

    float* hw = HS + wid * (BPW * JSTR);
    const int bbase = blockIdx.x * BPB + wid * BPW;

    u64 acc[2][4][4];   // [pass][r][dpair]

    // ---- prework: two passes, 4 b each; lane owns b = bbase + p*4 + j ----
#pragma unroll
    for (int p = 0; p < 2; p++) {
        const int jrow = p * 4 + j;
        int b = bbase + jrow;
        b = (b < B) ? b : (B - 1);

        const int act = action[b];
        const float4 A0 = *(const float4*)&MA[act * 12 + 0];
        const float4 A1 = *(const float4*)&MA[act * 12 + 4];
        const float  A2 = MA[act * 12 + 8];

        // front-load state for this pass's 4 channels
        float4 sA[4], sB[4];
#pragma unroll
        for (int r = 0; r < 4; r++) {
            const int c = og + 8 * r;
            const float4* sp = (const float4*)(state + (((size_t)b * NCH + c) << 3));
            sA[r] = sp[0];
            sB[r] = sp[1];
        }

#pragma unroll
        for (int r = 0; r < 4; r++) {
            const int c = og + 8 * r;
            const float s0 = sA[r].x, s1 = sA[r].y, s2 = sA[r].z, s3 = sA[r].w;
            const float s4 = sB[r].x, s5 = sB[r].y, s6 = sB[r].z, s7 = sB[r].w;

            // x = R s R~ : scalar/pseudo invariant; vector + dual-bivector rotate
            float xv1, xv2, xv3, xb1, xb2, xb3;
            mat_apply(A0, A1, A2, s1, s2, s4, xv1, xv2, xv3);
            mat_apply(A0, A1, A2, s6, -s5, s3, xb1, xb2, xb3);
            const float x0 = s0, x1 = xv1, x2 = xv2, x3 = xb3,
                        x4 = xv3, x5 = -xb2, x6 = xb1, x7 = s7;

            float nn = 1e-6f;
            nn = fmaf(x0, x0, nn); nn = fmaf(x1, x1, nn);
            nn = fmaf(x2, x2, nn); nn = fmaf(x3, x3, nn);
            nn = fmaf(x4, x4, nn); nn = fmaf(x5, x5, nn);
            nn = fmaf(x6, x6, nn); nn = fmaf(x7, x7, nn);
            const float inv = rsqrtf(nn) * NSC[c];
            const float g0 = x0 * inv;
            const float gate = 0.5f * (1.0f + erff(g0 * 0.70710678118654752f));
            const float sc = inv * gate;
            const float h0 = x0 * sc, h1 = x1 * sc, h2 = x2 * sc, h3 = x3 * sc;
            const float h4 = x4 * sc, h5 = x5 * sc, h6 = x6 * sc, h7 = x7 * sc;

            const float4 C0 = *(const float4*)&MC[c * 12 + 0];
            const float4 C1 = *(const float4*)&MC[c * 12 + 4];
            const float  C2 = MC[c * 12 + 8];
            float yv1, yv2, yv3, yb1, yb2, yb3;
            mat_apply(C0, C1, C2, h1, h2, h4, yv1, yv2, yv3);
            mat_apply(C0, C1, C2, h6, -h5, h3, yb1, yb2, yb3);

            float* hp = hw + jrow * JSTR + c * CSTR;
            *(float4*)(hp + 0) = make_float4(h0, yv1, yv2, yb3);
            *(float4*)(hp + 4) = make_float4(yv3, -yb2, yb1, h7);

            acc[p][r][0] = pack2(x0 + LB[c], x1);
            acc[p][r][1] = pack2(x2, x3);
            acc[p][r][2] = pack2(x4, x5);
            acc[p][r][3] = pack2(x6, x7);
        }
    }
    __syncwarp();

    // ---- grade-tied channel mix: W loaded once per (i,r), reused for 2 b ----
#pragma unroll 4
    for (int i = 0; i < NCH; i++) {
        const float* hp0 = hw + j * JSTR + i * CSTR;         // pass 0 row
        const float* hp1 = hw + (4 + j) * JSTR + i * CSTR;   // pass 1 row
        const ulonglong2 hA0 = *(const ulonglong2*)(hp0 + 0);
        const ulonglong2 hB0 = *(const ulonglong2*)(hp0 + 4);
        const ulonglong2 hA1 = *(const ulonglong2*)(hp1 + 0);
        const ulonglong2 hB1 = *(const ulonglong2*)(hp1 + 4);
#pragma unroll
        for (int r = 0; r < 4; r++) {
            const float4 w = *(const float4*)&WT[i * 128 + (og + 8 * r) * 4];
            const u64 w01 = pack2(w.x, w.y);
            const u64 w12 = pack2(w.y, w.z);
            const u64 w23 = pack2(w.z, w.w);
            fma2(acc[0][r][0], hA0.x, w01);
            fma2(acc[0][r][1], hA0.y, w12);
            fma2(acc[0][r][2], hB0.x, w12);
            fma2(acc[0][r][3], hB0.y, w23);
            fma2(acc[1][r][0], hA1.x, w01);
            fma2(acc[1][r][1], hA1.y, w12);
            fma2(acc[1][r][2], hB1.x, w12);
            fma2(acc[1][r][3], hB1.y, w23);
        }
    }

    // ---- epilogue: next_state + reward for both passes ----
#pragma unroll
    for (int p = 0; p < 2; p++) {
        const int b = bbase + p * 4 + j;
        const bool valid = (b < B);
        if (valid) {
#pragma unroll
            for (int r = 0; r < 4; r++) {
                const int c = og + 8 * r;
                float* ns = out + B + (((size_t)b * NCH + c) << 3);
                ulonglong2 v0; v0.x = acc[p][r][0]; v0.y = acc[p][r][1];
                ulonglong2 v1; v1.x = acc[p][r][2]; v1.y = acc[p][r][3];
                *(ulonglong2*)(ns + 0) = v0;
                *(ulonglong2*)(ns + 4) = v1;
            }
        }
        float rv = 0.f;
#pragma unroll
        for (int r = 0; r < 4; r++) rv = fmaf(low2(acc[p][r][0]), RW[og + 8 * r], rv);
#pragma unroll
        for (int off = 4; off; off >>= 1) rv += __shfl_xor_sync(0xffffffffu, rv, off);
        if (og == 0 && valid) out[b] = rv + RB[0];
    }
}

extern "C" void kernel_launch(void* const* d_in, const int* in_sizes, int n_in,
                              void* d_out, int out_size) {
    const float* state      = (const float*)d_in[0];
    const int*   action     = (const int*)  d_in[1];
    const float* act_bv     = (const float*)d_in[2];
    const float* norm_scale = (const float*)d_in[3];
    const float* rotor_bv   = (const float*)d_in[4];
    const float* lin_W      = (const float*)d_in[5];
    const float* lin_b      = (const float*)d_in[6];
    const float* reward_W   = (const float*)d_in[7];
    const float* reward_b   = (const float*)d_in[8];
    float* out = (float*)d_out;

    const int B = in_sizes[1];               // action count
    const int blocks = (B + BPB - 1) / BPB;  // 32 batch rows per block

    cudaFuncSetAttribute(dynamics_kernel,
                         cudaFuncAttributeMaxDynamicSharedMemorySize, SMEM_BYTES);
    dynamics_kernel<<<blocks, 128, SMEM_BYTES>>>(state, action, act_bv, norm_scale,
                                                 rotor_bv, lin_W, lin_b, reward_W,
                                                 reward_b, out, B);
}

// round 9
// speedup vs baseline: 1.8486x; 1.1468x over previous
#include <cuda_runtime.h>
#include <math.h>

typedef unsigned long long u64;

// ---- packed f32x2 helpers ----
__device__ __forceinline__ u64 pack2(float lo, float hi) {
    u64 r; asm("mov.b64 %0, {%1, %2};" : "=l"(r) : "f"(lo), "f"(hi)); return r;
}
__device__ __forceinline__ float low2(u64 v) {
    float lo, hi; asm("mov.b64 {%0, %1}, %2;" : "=f"(lo), "=f"(hi) : "l"(v)); return lo;
}
__device__ __forceinline__ void fma2(u64& d, u64 a, u64 b) {
    asm("fma.rn.f32x2 %0, %1, %2, %0;" : "+l"(d) : "l"(a), "l"(b));
}

// rotor_exp of bivector -> components {scalar, e12, e13, e23}
__device__ __forceinline__ void rotor_exp4(float b0, float b1, float b2, float r[4]) {
    float t2 = fmaf(b0, b0, fmaf(b1, b1, b2 * b2));
    float th = sqrtf(t2);
    float sn, cs;
    sincosf(th, &sn, &cs);
    float sinc = (th > 1e-6f) ? sn / fmaxf(th, 1e-6f) : 1.0f;
    r[0] = cs; r[1] = sinc * b0; r[2] = sinc * b1; r[3] = sinc * b2;
}

// 3x3 rotation matrix from unit rotor u = (scalar, e12, e13, e23).
__device__ __forceinline__ void rotor_to_mat(const float u[4], float m[9]) {
    const float qw = u[0], qx = -u[3], qy = u[2], qz = -u[1];
    const float x2 = qx + qx, y2 = qy + qy, z2 = qz + qz;
    const float xx = qx * x2, yy = qy * y2, zz = qz * z2;
    const float xy = qx * y2, xz = qx * z2, yz = qy * z2;
    const float wx = qw * x2, wy = qw * y2, wz = qw * z2;
    m[0] = 1.f - (yy + zz); m[1] = xy - wz;        m[2] = xz + wy;
    m[3] = xy + wz;         m[4] = 1.f - (xx + zz); m[5] = yz - wx;
    m[6] = xz - wy;         m[7] = yz + wx;        m[8] = 1.f - (xx + yy);
}

__device__ __forceinline__ void mat_apply(const float4 A0, const float4 A1, const float A2,
                                          float v1, float v2, float v3,
                                          float& o1, float& o2, float& o3) {
    o1 = fmaf(A0.x, v1, fmaf(A0.y, v2, A0.z * v3));
    o2 = fmaf(A0.w, v1, fmaf(A1.x, v2, A1.y * v3));
    o3 = fmaf(A1.z, v1, fmaf(A1.w, v2, A2  * v3));
}

#define NCH  32
#define WPB  4            // warps per block (128 threads)
#define BPW  8            // batch rows per warp (2 per lane)
#define BPB  (WPB * BPW)  // 32 b per block
#define JSTR 260          // h row stride (floats): ==4 mod 32 banks, 16B aligned
#define CSTR 8            // h channel stride (floats), tight pack + parity swizzle

// dynamic smem layout (float offsets)
#define OFF_WT   0                       // 4096
#define OFF_HS   4096                    // WPB*BPW*JSTR = 8320
#define OFF_MC   (OFF_HS + WPB*BPW*JSTR) // 32*12
#define OFF_MA   (OFF_MC + 384)          // 8*12 (5 used)
#define OFF_NSC  (OFF_MA + 96)
#define OFF_LB   (OFF_NSC + 32)
#define OFF_RW   (OFF_LB + 32)
#define OFF_RB   (OFF_RW + 32)
#define SMEM_FLOATS (OFF_RB + 4)
#define SMEM_BYTES  (SMEM_FLOATS * 4)    // ~52KB -> 4 blocks/SM

__global__ __launch_bounds__(128, 4) void dynamics_kernel(
    const float* __restrict__ state,       // [B, 32, 8]
    const int*   __restrict__ action,      // [B]
    const float* __restrict__ act_bv,      // [5, 3]
    const float* __restrict__ norm_scale,  // [32]
    const float* __restrict__ rotor_bv,    // [32, 3]
    const float* __restrict__ lin_W,       // [32, 32, 4]
    const float* __restrict__ lin_b,       // [32]
    const float* __restrict__ reward_W,    // [1, 32]
    const float* __restrict__ reward_b,    // [1]
    float* __restrict__ out,               // [B] reward, then [B,32,8] next_state
    int B)
{
    extern __shared__ __align__(16) float dsm[];
    float* WT  = dsm + OFF_WT;   // WT[i*128 + o*4 + k]
    float* HS  = dsm + OFF_HS;
    float* MC  = dsm + OFF_MC;   // MC[c*12 + 0..8]
    float* MA  = dsm + OFF_MA;   // MA[a*12 + 0..8]
    float* NSC = dsm + OFF_NSC;
    float* LB  = dsm + OFF_LB;
    float* RW  = dsm + OFF_RW;
    float* RB  = dsm + OFF_RB;

    const int tid  = threadIdx.x;
    const int lane = tid & 31;
    const int wid  = tid >> 5;
    const int j    = lane >> 3;   // batch row within warp (pass adds +4)
    const int og   = lane & 7;    // channel octet index
    const int swA  = (og & 4) ? 4 : 0;   // parity swizzle: store half-offsets
    const int swB  = 4 - swA;

    // ---- stage params ----
    for (int s = tid; s < NCH * 128; s += 128) {
        const int o = s >> 7, i = (s >> 2) & 31, k = s & 3;
        WT[i * 128 + o * 4 + k] = lin_W[s];
    }
    if (tid < NCH) {
        NSC[tid] = norm_scale[tid];
        LB[tid]  = lin_b[tid];
        RW[tid]  = reward_W[tid];
        float r[4], m[9];
        rotor_exp4(-0.5f * rotor_bv[tid * 3 + 0],
                   -0.5f * rotor_bv[tid * 3 + 1],
                   -0.5f * rotor_bv[tid * 3 + 2], r);
        rotor_to_mat(r, m);
#pragma unroll
        for (int e = 0; e < 9; e++) MC[tid * 12 + e] = m[e];
    }
    if (tid >= 32 && tid < 37) {
        const int a = tid - 32;
        float r[4], m[9];
        rotor_exp4(-0.5f * act_bv[a * 3 + 0],
                   -0.5f * act_bv[a * 3 + 1],
                   -0.5f * act_bv[a * 3 + 2], r);
        rotor_to_mat(r, m);
#pragma unroll
        for (int e = 0; e < 9; e++) MA[a * 12 + e] = m[e];
    }
    if (tid == 40) RB[0] = reward_b[0];
    __syncthreads();

    float* hw = HS + wid * (BPW * JSTR);
    const int bbase = blockIdx.x * BPB + wid * BPW;

    u64 acc[2][4][4];   // [pass][r][dpair]

    // ---- prework: two passes, 4 b each; lane owns b = bbase + p*4 + j ----
#pragma unroll
    for (int p = 0; p < 2; p++) {
        const int jrow = p * 4 + j;
        int b = bbase + jrow;
        b = (b < B) ? b : (B - 1);

        const int act = action[b];
        const float4 A0 = *(const float4*)&MA[act * 12 + 0];
        const float4 A1 = *(const float4*)&MA[act * 12 + 4];
        const float  A2 = MA[act * 12 + 8];

        float4 sA[4], sB[4];
#pragma unroll
        for (int r = 0; r < 4; r++) {
            const int c = og + 8 * r;
            const float4* sp = (const float4*)(state + (((size_t)b * NCH + c) << 3));
            sA[r] = sp[0];
            sB[r] = sp[1];
        }

#pragma unroll
        for (int r = 0; r < 4; r++) {
            const int c = og + 8 * r;
            const float s0 = sA[r].x, s1 = sA[r].y, s2 = sA[r].z, s3 = sA[r].w;
            const float s4 = sB[r].x, s5 = sB[r].y, s6 = sB[r].z, s7 = sB[r].w;

            // x = R s R~ : scalar/pseudo invariant; vector + dual-bivector rotate
            float xv1, xv2, xv3, xb1, xb2, xb3;
            mat_apply(A0, A1, A2, s1, s2, s4, xv1, xv2, xv3);
            mat_apply(A0, A1, A2, s6, -s5, s3, xb1, xb2, xb3);
            const float x0 = s0, x1 = xv1, x2 = xv2, x3 = xb3,
                        x4 = xv3, x5 = -xb2, x6 = xb1, x7 = s7;

            float nn = 1e-6f;
            nn = fmaf(x0, x0, nn); nn = fmaf(x1, x1, nn);
            nn = fmaf(x2, x2, nn); nn = fmaf(x3, x3, nn);
            nn = fmaf(x4, x4, nn); nn = fmaf(x5, x5, nn);
            nn = fmaf(x6, x6, nn); nn = fmaf(x7, x7, nn);
            const float inv = rsqrtf(nn) * NSC[c];
            const float g0 = x0 * inv;
            const float gate = 0.5f * (1.0f + erff(g0 * 0.70710678118654752f));
            const float sc = inv * gate;
            const float h0 = x0 * sc, h1 = x1 * sc, h2 = x2 * sc, h3 = x3 * sc;
            const float h4 = x4 * sc, h5 = x5 * sc, h6 = x6 * sc, h7 = x7 * sc;

            const float4 C0 = *(const float4*)&MC[c * 12 + 0];
            const float4 C1 = *(const float4*)&MC[c * 12 + 4];
            const float  C2 = MC[c * 12 + 8];
            float yv1, yv2, yv3, yb1, yb2, yb3;
            mat_apply(C0, C1, C2, h1, h2, h4, yv1, yv2, yv3);
            mat_apply(C0, C1, C2, h6, -h5, h3, yb1, yb2, yb3);

            // parity-swizzled store: halves swapped when c&4
            float* hp = hw + jrow * JSTR + c * CSTR;
            *(float4*)(hp + swA) = make_float4(h0, yv1, yv2, yb3);
            *(float4*)(hp + swB) = make_float4(yv3, -yb2, yb1, h7);

            acc[p][r][0] = pack2(x0 + LB[c], x1);
            acc[p][r][1] = pack2(x2, x3);
            acc[p][r][2] = pack2(x4, x5);
            acc[p][r][3] = pack2(x6, x7);
        }
    }
    __syncwarp();

    // ---- grade-tied channel mix: W loaded once per (i,r), reused for 2 b ----
    // unroll by 8 so (i&4) is compile-time -> read swizzle is free
#pragma unroll 8
    for (int i = 0; i < NCH; i++) {
        const int rsA = (i & 4) ? 4 : 0;   // compile-time under unroll-8
        const int rsB = 4 - rsA;
        const float* hp0 = hw + j * JSTR + i * CSTR;         // pass 0 row
        const float* hp1 = hw + (4 + j) * JSTR + i * CSTR;   // pass 1 row
        const ulonglong2 hA0 = *(const ulonglong2*)(hp0 + rsA);
        const ulonglong2 hB0 = *(const ulonglong2*)(hp0 + rsB);
        const ulonglong2 hA1 = *(const ulonglong2*)(hp1 + rsA);
        const ulonglong2 hB1 = *(const ulonglong2*)(hp1 + rsB);
#pragma unroll
        for (int r = 0; r < 4; r++) {
            const float4 w = *(const float4*)&WT[i * 128 + (og + 8 * r) * 4];
            const u64 w01 = pack2(w.x, w.y);
            const u64 w12 = pack2(w.y, w.z);
            const u64 w23 = pack2(w.z, w.w);
            fma2(acc[0][r][0], hA0.x, w01);
            fma2(acc[0][r][1], hA0.y, w12);
            fma2(acc[0][r][2], hB0.x, w12);
            fma2(acc[0][r][3], hB0.y, w23);
            fma2(acc[1][r][0], hA1.x, w01);
            fma2(acc[1][r][1], hA1.y, w12);
            fma2(acc[1][r][2], hB1.x, w12);
            fma2(acc[1][r][3], hB1.y, w23);
        }
    }

    // ---- epilogue: next_state + reward for both passes ----
#pragma unroll
    for (int p = 0; p < 2; p++) {
        const int b = bbase + p * 4 + j;
        const bool valid = (b < B);
        if (valid) {
#pragma unroll
            for (int r = 0; r < 4; r++) {
                const int c = og + 8 * r;
                float* ns = out + B + (((size_t)b * NCH + c) << 3);
                ulonglong2 v0; v0.x = acc[p][r][0]; v0.y = acc[p][r][1];
                ulonglong2 v1; v1.x = acc[p][r][2]; v1.y = acc[p][r][3];
                *(ulonglong2*)(ns + 0) = v0;
                *(ulonglong2*)(ns + 4) = v1;
            }
        }
        float rv = 0.f;
#pragma unroll
        for (int r = 0; r < 4; r++) rv = fmaf(low2(acc[p][r][0]), RW[og + 8 * r], rv);
#pragma unroll
        for (int off = 4; off; off >>= 1) rv += __shfl_xor_sync(0xffffffffu, rv, off);
        if (og == 0 && valid) out[b] = rv + RB[0];
    }
}

extern "C" void kernel_launch(void* const* d_in, const int* in_sizes, int n_in,
                              void* d_out, int out_size) {
    const float* state      = (const float*)d_in[0];
    const int*   action     = (const int*)  d_in[1];
    const float* act_bv     = (const float*)d_in[2];
    const float* norm_scale = (const float*)d_in[3];
    const float* rotor_bv   = (const float*)d_in[4];
    const float* lin_W      = (const float*)d_in[5];
    const float* lin_b      = (const float*)d_in[6];
    const float* reward_W   = (const float*)d_in[7];
    const float* reward_b   = (const float*)d_in[8];
    float* out = (float*)d_out;

    const int B = in_sizes[1];               // action count
    const int blocks = (B + BPB - 1) / BPB;  // 32 batch rows per block

    cudaFuncSetAttribute(dynamics_kernel,
                         cudaFuncAttributeMaxDynamicSharedMemorySize, SMEM_BYTES);
    dynamics_kernel<<<blocks, 128, SMEM_BYTES>>>(state, action, act_bv, norm_scale,
                                                 rotor_bv, lin_W, lin_b, reward_W,
                                                 reward_b, out, B);
}